// round 13
// baseline (speedup 1.0000x reference)
#include <cuda_runtime.h>
#include <cuda_bf16.h>
#include <math.h>
#include <stdint.h>

#define BB 2
#define NN 2048
#define DIM 1024
#define HH 16
#define DH 64
#define NNUL 2
#define JJ (NN + NNUL)
#define JJP 2112
#define SCALE 8.0f
#define LN_EPS 1e-5f
#define MM (BB * NN)

typedef __nv_bfloat16 bf16;

// ---------------- scratch ----------------------------------------------------
__device__ float g_xt[(size_t)MM * DIM];
__device__ float g_xn[(size_t)MM * DIM];
__device__ float g_wqt[(size_t)DIM * DIM];        // transposed [N][K], tf32
__device__ float g_wkvt[(size_t)2 * DIM * DIM];   // transposed [N][K], tf32
__device__ float g_wot[(size_t)DIM * DIM];        // transposed [N][K], tf32
__device__ float g_qraw[(size_t)MM * DIM];
__device__ float g_kvraw[(size_t)MM * 2 * DIM];
__device__ float g_q[(size_t)BB * HH * NN * DH];
__device__ float g_ao[(size_t)MM * DIM];
__device__ bf16 g_kh[(size_t)BB * HH * JJP * DH];
__device__ bf16 g_kl[(size_t)BB * HH * JJP * DH];
__device__ bf16 g_vth[(size_t)BB * HH * DH * JJP];
__device__ bf16 g_vtl[(size_t)BB * HH * DH * JJP];

__device__ __forceinline__ uint32_t to_tf32(float f) {
    uint32_t u;
    asm("cvt.rna.tf32.f32 %0, %1;" : "=r"(u) : "f"(f));
    return u;
}
__device__ __forceinline__ float tf32f(float f) { return __uint_as_float(to_tf32(f)); }

// ---------------- weight transpose + tf32 round: [K][N] -> [N][K] -------------
__global__ void wtconv_kernel(const float* __restrict__ W, float* __restrict__ Wt,
                              int K, int N) {
    __shared__ float t[32][33];
    int tx = threadIdx.x, ty = threadIdx.y;
    int n0 = blockIdx.x * 32, k0 = blockIdx.y * 32;
#pragma unroll
    for (int e = 0; e < 4; e++)
        t[ty + 8 * e][tx] = W[(size_t)(k0 + ty + 8 * e) * N + n0 + tx];
    __syncthreads();
#pragma unroll
    for (int e = 0; e < 4; e++) {
        float v = t[tx][ty + 8 * e];
        int n = n0 + ty + 8 * e, k = k0 + tx;
        Wt[(size_t)n * K + k] = tf32f(v);
    }
}

// ---------------- LayerNorm (emits tf32 xn AND tf32 x) ------------------------
__global__ void ln_kernel(const float* __restrict__ x, const float* __restrict__ gma,
                          const float* __restrict__ bta) {
    int row = blockIdx.x;
    const float* xr = x + (size_t)row * DIM;
    float vals[4];
    float s = 0.f, ss = 0.f;
#pragma unroll
    for (int i = 0; i < 4; i++) {
        float v = xr[threadIdx.x + i * 256];
        vals[i] = v;
        s += v;
        ss += v * v;
    }
#pragma unroll
    for (int off = 16; off; off >>= 1) {
        s += __shfl_xor_sync(0xffffffffu, s, off);
        ss += __shfl_xor_sync(0xffffffffu, ss, off);
    }
    __shared__ float rs[8], rss[8];
    int w = threadIdx.x >> 5;
    if ((threadIdx.x & 31) == 0) { rs[w] = s; rss[w] = ss; }
    __syncthreads();
    if (threadIdx.x < 32) {
        float a = (threadIdx.x < 8) ? rs[threadIdx.x] : 0.f;
        float b2 = (threadIdx.x < 8) ? rss[threadIdx.x] : 0.f;
#pragma unroll
        for (int off = 4; off; off >>= 1) {
            a += __shfl_xor_sync(0xffffffffu, a, off);
            b2 += __shfl_xor_sync(0xffffffffu, b2, off);
        }
        if (threadIdx.x == 0) { rs[0] = a; rss[0] = b2; }
    }
    __syncthreads();
    float mu = rs[0] * (1.0f / DIM);
    float var = rss[0] * (1.0f / DIM) - mu * mu;
    float inv = rsqrtf(var + LN_EPS);
#pragma unroll
    for (int i = 0; i < 4; i++) {
        int d = threadIdx.x + i * 256;
        g_xt[(size_t)row * DIM + d] = tf32f(vals[i]);
        g_xn[(size_t)row * DIM + d] = tf32f((vals[i] - mu) * inv * gma[d] + bta[d]);
    }
}

// ---------------- TF32 GEMM core (K=DIM, B stored [N][K], ldmatrix frags) ----
#define TBM 128
#define TBN 128
#define TBK 32
#define TSTR 36
#define TILE_FLOATS (128 * TSTR)
#define STAGE_FLOATS (2 * TILE_FLOATS)
#define GEMM_SMEM_BYTES (2 * STAGE_FLOATS * 4)
#define GK DIM
#define GTILES (GK / TBK)

__device__ __forceinline__ void cp_async16(void* sdst, const void* gsrc) {
    uint32_t sa = (uint32_t)__cvta_generic_to_shared(sdst);
    asm volatile("cp.async.cg.shared.global [%0], [%1], 16;\n" :: "r"(sa), "l"(gsrc));
}
__device__ __forceinline__ void cp_commit() {
    asm volatile("cp.async.commit_group;\n" ::: "memory");
}
__device__ __forceinline__ void cp_wait0() {
    asm volatile("cp.async.wait_group 0;\n" ::: "memory");
}
__device__ __forceinline__ void cp_wait1() {
    asm volatile("cp.async.wait_group 1;\n" ::: "memory");
}
#define LDSM_X4(r0, r1, r2, r3, addr)                                        \
    asm volatile("ldmatrix.sync.aligned.m8n8.x4.shared.b16 {%0,%1,%2,%3}, [%4];" \
        : "=r"(r0), "=r"(r1), "=r"(r2), "=r"(r3) : "r"(addr))

__device__ __forceinline__ void gemm_body(const float* __restrict__ A,
                                          const float* __restrict__ Bt,
                                          float* __restrict__ C,
                                          int N, int row0, int col0, float* smem) {
    int tid = threadIdx.x;
    int lane = tid & 31;
    int warp = tid >> 5;
    int wm = warp >> 2;
    int wn = warp & 3;

    float acc[4][4][4];
#pragma unroll
    for (int i = 0; i < 4; i++)
#pragma unroll
        for (int j = 0; j < 4; j++)
#pragma unroll
            for (int r = 0; r < 4; r++) acc[i][j][r] = 0.f;

    int s_r = tid >> 3;
    int s_c4 = (tid & 7) * 4;

    uint32_t smem_u32 = (uint32_t)__cvta_generic_to_shared(smem);

    int ltile = lane >> 3;
    int lrow = lane & 7;
    uint32_t aBase[4];
#pragma unroll
    for (int mt = 0; mt < 4; mt++) {
        int r = wm * 64 + mt * 16 + (ltile & 1) * 8 + lrow;
        aBase[mt] = (uint32_t)((r * TSTR + (ltile >> 1) * 4) * 4);
    }
    uint32_t bBase[2];
#pragma unroll
    for (int p = 0; p < 2; p++) {
        int r = wn * 32 + p * 16 + (ltile >> 1) * 8 + lrow;
        bBase[p] = (uint32_t)(TILE_FLOATS * 4 + (r * TSTR + (ltile & 1) * 4) * 4);
    }

    {
        float* As = smem;
        float* Bs = smem + TILE_FLOATS;
#pragma unroll
        for (int t = 0; t < 4; t++) {
            int r = s_r + t * 32;
            cp_async16(&As[r * TSTR + s_c4], &A[(size_t)(row0 + r) * GK + s_c4]);
            cp_async16(&Bs[r * TSTR + s_c4], &Bt[(size_t)(col0 + r) * GK + s_c4]);
        }
        cp_commit();
    }

    for (int kt = 0; kt < GTILES; kt++) {
        cp_wait0();
        __syncthreads();
        if (kt + 1 < GTILES) {
            float* As = smem + ((kt + 1) & 1) * STAGE_FLOATS;
            float* Bs = As + TILE_FLOATS;
            int kg = (kt + 1) * TBK;
#pragma unroll
            for (int t = 0; t < 4; t++) {
                int r = s_r + t * 32;
                cp_async16(&As[r * TSTR + s_c4], &A[(size_t)(row0 + r) * GK + kg + s_c4]);
                cp_async16(&Bs[r * TSTR + s_c4], &Bt[(size_t)(col0 + r) * GK + kg + s_c4]);
            }
            cp_commit();
        }
        uint32_t stage = smem_u32 + (uint32_t)((kt & 1) * STAGE_FLOATS * 4);
#pragma unroll
        for (int ks = 0; ks < 4; ks++) {
            uint32_t koff = (uint32_t)(ks * 8 * 4);
            uint32_t af[4][4], bf[4][2];
#pragma unroll
            for (int mt = 0; mt < 4; mt++)
                LDSM_X4(af[mt][0], af[mt][1], af[mt][2], af[mt][3],
                        stage + aBase[mt] + koff);
#pragma unroll
            for (int p = 0; p < 2; p++)
                LDSM_X4(bf[2 * p][0], bf[2 * p][1], bf[2 * p + 1][0], bf[2 * p + 1][1],
                        stage + bBase[p] + koff);
#pragma unroll
            for (int mt = 0; mt < 4; mt++)
#pragma unroll
                for (int nt = 0; nt < 4; nt++) {
                    asm volatile(
                        "mma.sync.aligned.m16n8k8.row.col.f32.tf32.tf32.f32 "
                        "{%0,%1,%2,%3}, {%4,%5,%6,%7}, {%8,%9}, {%0,%1,%2,%3};"
                        : "+f"(acc[mt][nt][0]), "+f"(acc[mt][nt][1]),
                          "+f"(acc[mt][nt][2]), "+f"(acc[mt][nt][3])
                        : "r"(af[mt][0]), "r"(af[mt][1]), "r"(af[mt][2]), "r"(af[mt][3]),
                          "r"(bf[nt][0]), "r"(bf[nt][1]));
                }
        }
    }

    int fr = lane >> 2;
    int fc = lane & 3;
#pragma unroll
    for (int mt = 0; mt < 4; mt++) {
        int row = row0 + wm * 64 + mt * 16 + fr;
#pragma unroll
        for (int nt = 0; nt < 4; nt++) {
            int col = col0 + wn * 32 + nt * 8 + fc * 2;
            *(float2*)&C[(size_t)row * N + col] = make_float2(acc[mt][nt][0], acc[mt][nt][1]);
            *(float2*)&C[(size_t)(row + 8) * N + col] = make_float2(acc[mt][nt][2], acc[mt][nt][3]);
        }
    }
}

__global__ void __launch_bounds__(256, 2)
tf32gemm_qkv() {
    extern __shared__ float smem[];
    const float* A;
    const float* B;
    float* C;
    int N, col0;
    if (blockIdx.x < 8) {
        A = g_xn; B = g_wqt; C = g_qraw; N = DIM; col0 = blockIdx.x * TBN;
    } else {
        A = g_xt; B = g_wkvt; C = g_kvraw; N = 2 * DIM; col0 = (blockIdx.x - 8) * TBN;
    }
    gemm_body(A, B, C, N, blockIdx.y * TBM, col0, smem);
}

__global__ void __launch_bounds__(256, 2)
tf32gemm_o(float* __restrict__ out) {
    extern __shared__ float smem[];
    gemm_body(g_ao, g_wot, out, DIM, blockIdx.y * TBM, blockIdx.x * TBN, smem);
}

// ---------------- preps ------------------------------------------------------
__global__ void qprep_kernel(const float* __restrict__ qs) {
    int gw = blockIdx.x * 4 + (threadIdx.x >> 5);
    int lane = threadIdx.x & 31;
    int h = gw % HH;
    int n = (gw / HH) % NN;
    int b = gw / (HH * NN);
    const float* src = g_qraw + (size_t)(b * NN + n) * DIM + h * DH;
    float v0 = src[lane], v1 = src[lane + 32];
    float ss = v0 * v0 + v1 * v1;
#pragma unroll
    for (int off = 16; off; off >>= 1) ss += __shfl_xor_sync(0xffffffffu, ss, off);
    float inv = 1.0f / fmaxf(sqrtf(ss), 1e-12f);
    float* dst = g_q + (size_t)((b * HH + h) * NN + n) * DH;
    dst[lane] = v0 * inv * qs[lane];
    dst[lane + 32] = v1 * inv * qs[lane + 32];
}

__global__ void kvprep_kernel(const float* __restrict__ ks) {
    int gw = blockIdx.x * 4 + (threadIdx.x >> 5);
    int lane = threadIdx.x & 31;
    int h = gw % HH;
    int n = (gw / HH) % NN;
    int b = gw / (HH * NN);
    const float* row = g_kvraw + (size_t)(b * NN + n) * (2 * DIM);
    float k0 = row[h * DH + lane], k1 = row[h * DH + lane + 32];
    float v0 = row[DIM + h * DH + lane], v1 = row[DIM + h * DH + lane + 32];
    float ss = k0 * k0 + k1 * k1;
#pragma unroll
    for (int off = 16; off; off >>= 1) ss += __shfl_xor_sync(0xffffffffu, ss, off);
    float inv = 1.0f / fmaxf(sqrtf(ss), 1e-12f);
    k0 = k0 * inv * ks[lane];
    k1 = k1 * inv * ks[lane + 32];
    int j = n + NNUL;
    size_t kb = ((size_t)(b * HH + h) * JJP + j) * DH;
    bf16 h0 = __float2bfloat16_rn(k0);
    bf16 h1 = __float2bfloat16_rn(k1);
    g_kh[kb + lane] = h0;
    g_kh[kb + lane + 32] = h1;
    g_kl[kb + lane] = __float2bfloat16_rn(k0 - __bfloat162float(h0));
    g_kl[kb + lane + 32] = __float2bfloat16_rn(k1 - __bfloat162float(h1));
    size_t vb = (size_t)(b * HH + h) * DH * JJP;
    bf16 vh0 = __float2bfloat16_rn(v0);
    bf16 vh1 = __float2bfloat16_rn(v1);
    g_vth[vb + (size_t)lane * JJP + j] = vh0;
    g_vth[vb + (size_t)(lane + 32) * JJP + j] = vh1;
    g_vtl[vb + (size_t)lane * JJP + j] = __float2bfloat16_rn(v0 - __bfloat162float(vh0));
    g_vtl[vb + (size_t)(lane + 32) * JJP + j] = __float2bfloat16_rn(v1 - __bfloat162float(vh1));
}

__global__ void nullprep_kernel(const float* __restrict__ null_kv,
                                const float* __restrict__ ks) {
    int w = threadIdx.x >> 5;
    int lane = threadIdx.x & 31;
    int h = w / NNUL;
    int t = w % NNUL;
    const float* base = null_kv + (size_t)h * (2 * NNUL) * DH;
    float k0 = base[(2 * t) * DH + lane];
    float k1 = base[(2 * t) * DH + lane + 32];
    float v0 = base[(2 * t + 1) * DH + lane];
    float v1 = base[(2 * t + 1) * DH + lane + 32];
    float ss = k0 * k0 + k1 * k1;
#pragma unroll
    for (int off = 16; off; off >>= 1) ss += __shfl_xor_sync(0xffffffffu, ss, off);
    float inv = 1.0f / fmaxf(sqrtf(ss), 1e-12f);
    k0 = k0 * inv * ks[lane];
    k1 = k1 * inv * ks[lane + 32];
    bf16 kh0 = __float2bfloat16_rn(k0), kh1 = __float2bfloat16_rn(k1);
    bf16 kl0 = __float2bfloat16_rn(k0 - __bfloat162float(kh0));
    bf16 kl1 = __float2bfloat16_rn(k1 - __bfloat162float(kh1));
    bf16 vh0 = __float2bfloat16_rn(v0), vh1 = __float2bfloat16_rn(v1);
    bf16 vl0 = __float2bfloat16_rn(v0 - __bfloat162float(vh0));
    bf16 vl1 = __float2bfloat16_rn(v1 - __bfloat162float(vh1));
    for (int b = 0; b < BB; b++) {
        size_t kb = ((size_t)(b * HH + h) * JJP + t) * DH;
        g_kh[kb + lane] = kh0;
        g_kh[kb + lane + 32] = kh1;
        g_kl[kb + lane] = kl0;
        g_kl[kb + lane + 32] = kl1;
        size_t vb = (size_t)(b * HH + h) * DH * JJP;
        g_vth[vb + (size_t)lane * JJP + t] = vh0;
        g_vth[vb + (size_t)(lane + 32) * JJP + t] = vh1;
        g_vtl[vb + (size_t)lane * JJP + t] = vl0;
        g_vtl[vb + (size_t)(lane + 32) * JJP + t] = vl1;
    }
}

// ---------------- mma attention: 128 q-rows/CTA, double-buffered staging -----
#define KSTR 72
#define QSTR 68
#define TILE_HB (64 * KSTR * 2)           // 9216 bytes per array
#define BUF_B (4 * TILE_HB)               // Kh,Kl,Vh,Vl per stage = 36864
#define ATTN_SMEM (2 * BUF_B)             // 73728

#define MMA_BF16(C, A, B0, B1)                                              \
    asm volatile(                                                           \
        "mma.sync.aligned.m16n8k16.row.col.f32.bf16.bf16.f32 "              \
        "{%0,%1,%2,%3}, {%4,%5,%6,%7}, {%8,%9}, {%0,%1,%2,%3};"             \
        : "+f"(C[0]), "+f"(C[1]), "+f"(C[2]), "+f"(C[3])                    \
        : "r"(A[0]), "r"(A[1]), "r"(A[2]), "r"(A[3]), "r"(B0), "r"(B1))

__device__ __forceinline__ uint32_t pack_bf2(float a, float b) {
    __nv_bfloat162 t;
    t.x = __float2bfloat16_rn(a);
    t.y = __float2bfloat16_rn(b);
    return *(uint32_t*)&t;
}

__global__ void __launch_bounds__(256)
attn_mma_kernel() {
    extern __shared__ char sm[];
    float* Qs = (float*)sm;   // overlay on buffer 0 (used once before staging)

    int b = blockIdx.z, h = blockIdx.y;
    int qt = (gridDim.x - 1) - blockIdx.x;   // big tiles first
    int tid = threadIdx.x;
    int w = tid >> 5;
    int lane = tid & 31;
    int fr = lane >> 2;
    int fc = lane & 3;

    size_t qbase = (size_t)((b * HH + h) * NN + qt * 128) * DH;
    const char* kh_b = (const char*)(g_kh + (size_t)(b * HH + h) * JJP * DH);
    const char* kl_b = (const char*)(g_kl + (size_t)(b * HH + h) * JJP * DH);
    const char* vth_b = (const char*)(g_vth + (size_t)(b * HH + h) * DH * JJP);
    const char* vtl_b = (const char*)(g_vtl + (size_t)(b * HH + h) * DH * JJP);

    // ---- Q stage + fragment extraction (hi/lo bf16) ----
    for (int i = tid; i < 128 * 16; i += 256) {
        int r = i >> 4, c4 = (i & 15) * 4;
        *(float4*)&Qs[r * QSTR + c4] = *(const float4*)&g_q[qbase + (size_t)r * DH + c4];
    }
    __syncthreads();

    uint32_t qh[4][4], ql[4][4];
#pragma unroll
    for (int kc = 0; kc < 4; kc++) {
        int lr = w * 16 + fr;
        int c = kc * 16 + 2 * fc;
#pragma unroll
        for (int p = 0; p < 4; p++) {
            int rr = lr + (p & 1) * 8;
            int cc = c + (p >> 1) * 8;
            float x0 = Qs[rr * QSTR + cc], x1 = Qs[rr * QSTR + cc + 1];
            float h0 = __bfloat162float(__float2bfloat16_rn(x0));
            float h1 = __bfloat162float(__float2bfloat16_rn(x1));
            qh[kc][p] = pack_bf2(h0, h1);
            ql[kc][p] = pack_bf2(x0 - h0, x1 - h1);
        }
    }
    __syncthreads();   // Qs consumed; buffer 0 free for staging

    float O[8][4];
#pragma unroll
    for (int nb = 0; nb < 8; nb++)
#pragma unroll
        for (int r = 0; r < 4; r++) O[nb][r] = 0.f;

    float slope = exp2f(-0.5f * (float)(h + 1));
    int row0g = qt * 128 + w * 16 + fr;
    int row1g = row0g + 8;
    int my0 = row0g + NNUL, my1 = row1g + NNUL;
    float m0 = -1e30f, m1 = -1e30f, l0 = 0.f, l1 = 0.f;

    int nkeys = min(qt * 128 + 128 + NNUL, JJ);
    int T = (nkeys + 63) / 64;

    // staging macro: tile jt -> buffer s (8 cp.async per thread, 256 threads)
#define ATTN_STAGE(jt, s)                                                       \
    do {                                                                        \
        char* bp = sm + (s) * BUF_B;                                            \
        int j0s = (jt) * 64;                                                    \
        for (int i = tid; i < 64 * 8; i += 256) {                               \
            int r = i >> 3, c = i & 7;                                          \
            uint32_t doff = r * 144 + c * 16;                                   \
            cp_async16(bp + 0 * TILE_HB + doff, kh_b + (size_t)(j0s + r) * 128 + c * 16); \
            cp_async16(bp + 1 * TILE_HB + doff, kl_b + (size_t)(j0s + r) * 128 + c * 16); \
            cp_async16(bp + 2 * TILE_HB + doff, vth_b + (size_t)r * (JJP * 2) + j0s * 2 + c * 16); \
            cp_async16(bp + 3 * TILE_HB + doff, vtl_b + (size_t)r * (JJP * 2) + j0s * 2 + c * 16); \
        }                                                                       \
        cp_commit();                                                            \
    } while (0)

    ATTN_STAGE(0, 0);
    if (T > 1) ATTN_STAGE(1, 1);

    for (int t = 0; t < T; t++) {
        if (t + 1 < T) cp_wait1(); else cp_wait0();
        __syncthreads();
        char* bp = sm + (t & 1) * BUF_B;
        bf16* Kh = (bf16*)bp;
        bf16* Kl = (bf16*)(bp + TILE_HB);
        bf16* Vh = (bf16*)(bp + 2 * TILE_HB);
        bf16* Vl = (bf16*)(bp + 3 * TILE_HB);
        int j0 = t * 64;

        float S[8][4];
#pragma unroll
        for (int nb = 0; nb < 8; nb++)
#pragma unroll
            for (int r = 0; r < 4; r++) S[nb][r] = 0.f;

#pragma unroll
        for (int kc = 0; kc < 4; kc++) {
#pragma unroll
            for (int nb = 0; nb < 8; nb++) {
                int krow = nb * 8 + fr;
                int kcol = kc * 16 + 2 * fc;
                uint32_t b0h = *(uint32_t*)&Kh[krow * KSTR + kcol];
                uint32_t b1h = *(uint32_t*)&Kh[krow * KSTR + kcol + 8];
                uint32_t b0l = *(uint32_t*)&Kl[krow * KSTR + kcol];
                uint32_t b1l = *(uint32_t*)&Kl[krow * KSTR + kcol + 8];
                MMA_BF16(S[nb], qh[kc], b0h, b1h);
                MMA_BF16(S[nb], qh[kc], b0l, b1l);
                MMA_BF16(S[nb], ql[kc], b0h, b1h);
            }
        }

        float mt0 = -1e30f, mt1 = -1e30f;
#pragma unroll
        for (int nb = 0; nb < 8; nb++) {
#pragma unroll
            for (int e = 0; e < 2; e++) {
                int col = j0 + nb * 8 + 2 * fc + e;
                float s0 = S[nb][e] * SCALE + slope * (float)(col - my0);
                if (col > my0) s0 = -1e30f;
                S[nb][e] = s0;
                mt0 = fmaxf(mt0, s0);
                float s1 = S[nb][2 + e] * SCALE + slope * (float)(col - my1);
                if (col > my1) s1 = -1e30f;
                S[nb][2 + e] = s1;
                mt1 = fmaxf(mt1, s1);
            }
        }
#pragma unroll
        for (int off = 1; off <= 2; off <<= 1) {
            mt0 = fmaxf(mt0, __shfl_xor_sync(0xffffffffu, mt0, off));
            mt1 = fmaxf(mt1, __shfl_xor_sync(0xffffffffu, mt1, off));
        }
        float mn0 = fmaxf(m0, mt0), mn1 = fmaxf(m1, mt1);
        float c0 = __expf(m0 - mn0), c1 = __expf(m1 - mn1);
        m0 = mn0; m1 = mn1;

        float ps0 = 0.f, ps1 = 0.f;
#pragma unroll
        for (int nb = 0; nb < 8; nb++) {
#pragma unroll
            for (int e = 0; e < 2; e++) {
                float p0 = __expf(S[nb][e] - m0);
                float p1 = __expf(S[nb][2 + e] - m1);
                S[nb][e] = p0; S[nb][2 + e] = p1;
                ps0 += p0; ps1 += p1;
            }
        }
        l0 = l0 * c0 + ps0;
        l1 = l1 * c1 + ps1;
#pragma unroll
        for (int nb = 0; nb < 8; nb++) {
            O[nb][0] *= c0; O[nb][1] *= c0;
            O[nb][2] *= c1; O[nb][3] *= c1;
        }

        uint32_t ph[4][4], pl[4][4];
#pragma unroll
        for (int kc = 0; kc < 4; kc++) {
#pragma unroll
            for (int p = 0; p < 4; p++) {
                float x0 = S[2 * kc + (p >> 1)][(p & 1) * 2 + 0];
                float x1 = S[2 * kc + (p >> 1)][(p & 1) * 2 + 1];
                float h0 = __bfloat162float(__float2bfloat16_rn(x0));
                float h1 = __bfloat162float(__float2bfloat16_rn(x1));
                ph[kc][p] = pack_bf2(h0, h1);
                pl[kc][p] = pack_bf2(x0 - h0, x1 - h1);
            }
        }

#pragma unroll
        for (int kc = 0; kc < 4; kc++) {
#pragma unroll
            for (int nb = 0; nb < 8; nb++) {
                int drow = nb * 8 + fr;
                int kcol = kc * 16 + 2 * fc;
                uint32_t b0h = *(uint32_t*)&Vh[drow * KSTR + kcol];
                uint32_t b1h = *(uint32_t*)&Vh[drow * KSTR + kcol + 8];
                uint32_t b0l = *(uint32_t*)&Vl[drow * KSTR + kcol];
                uint32_t b1l = *(uint32_t*)&Vl[drow * KSTR + kcol + 8];
                MMA_BF16(O[nb], ph[kc], b0h, b1h);
                MMA_BF16(O[nb], ph[kc], b0l, b1l);
                MMA_BF16(O[nb], pl[kc], b0h, b1h);
            }
        }

        __syncthreads();   // all warps done with buffer (t&1) before restaging
        if (t + 2 < T) ATTN_STAGE(t + 2, t & 1);
    }

#pragma unroll
    for (int off = 1; off <= 2; off <<= 1) {
        l0 += __shfl_xor_sync(0xffffffffu, l0, off);
        l1 += __shfl_xor_sync(0xffffffffu, l1, off);
    }
    float i0 = 1.0f / l0, i1 = 1.0f / l1;
#pragma unroll
    for (int nb = 0; nb < 8; nb++) {
        int col = h * DH + nb * 8 + 2 * fc;
        *(float2*)&g_ao[(size_t)(b * NN + row0g) * DIM + col] =
            make_float2(tf32f(O[nb][0] * i0), tf32f(O[nb][1] * i0));
        *(float2*)&g_ao[(size_t)(b * NN + row1g) * DIM + col] =
            make_float2(tf32f(O[nb][2] * i1), tf32f(O[nb][3] * i1));
    }
}

// ---------------- launch -----------------------------------------------------
extern "C" void kernel_launch(void* const* d_in, const int* in_sizes, int n_in,
                              void* d_out, int out_size) {
    const float* x = (const float*)d_in[0];
    const float* norm_g = (const float*)d_in[1];
    const float* norm_b = (const float*)d_in[2];
    const float* Wq = (const float*)d_in[3];
    const float* Wkv = (const float*)d_in[4];
    const float* q_scale = (const float*)d_in[5];
    const float* k_scale = (const float*)d_in[6];
    const float* null_kv = (const float*)d_in[7];
    const float* Wout = (const float*)d_in[8];
    float* out = (float*)d_out;

    float *p_wqt, *p_wkvt, *p_wot;
    cudaGetSymbolAddress((void**)&p_wqt, g_wqt);
    cudaGetSymbolAddress((void**)&p_wkvt, g_wkvt);
    cudaGetSymbolAddress((void**)&p_wot, g_wot);

    static int smem_set = 0;
    if (!smem_set) {
        cudaFuncSetAttribute(tf32gemm_qkv, cudaFuncAttributeMaxDynamicSharedMemorySize,
                             GEMM_SMEM_BYTES);
        cudaFuncSetAttribute(tf32gemm_o, cudaFuncAttributeMaxDynamicSharedMemorySize,
                             GEMM_SMEM_BYTES);
        cudaFuncSetAttribute(attn_mma_kernel, cudaFuncAttributeMaxDynamicSharedMemorySize,
                             ATTN_SMEM);
        smem_set = 1;
    }

    wtconv_kernel<<<dim3(DIM / 32, DIM / 32), dim3(32, 8)>>>(Wq, p_wqt, DIM, DIM);
    wtconv_kernel<<<dim3(2 * DIM / 32, DIM / 32), dim3(32, 8)>>>(Wkv, p_wkvt, DIM, 2 * DIM);
    ln_kernel<<<MM, 256>>>(x, norm_g, norm_b);

    tf32gemm_qkv<<<dim3(24, MM / TBM), 256, GEMM_SMEM_BYTES>>>();

    wtconv_kernel<<<dim3(DIM / 32, DIM / 32), dim3(32, 8)>>>(Wout, p_wot, DIM, DIM);

    qprep_kernel<<<(BB * NN * HH) / 4, 128>>>(q_scale);
    kvprep_kernel<<<(BB * NN * HH) / 4, 128>>>(k_scale);
    nullprep_kernel<<<1, HH * NNUL * 32>>>(null_kv, k_scale);

    attn_mma_kernel<<<dim3(NN / 128, HH, BB), 256, ATTN_SMEM>>>();

    tf32gemm_o<<<dim3(DIM / TBN, MM / TBM), 256, GEMM_SMEM_BYTES>>>(out);
}

// round 14
// speedup vs baseline: 1.0689x; 1.0689x over previous
#include <cuda_runtime.h>
#include <cuda_bf16.h>
#include <math.h>
#include <stdint.h>

#define BB 2
#define NN 2048
#define DIM 1024
#define HH 16
#define DH 64
#define NNUL 2
#define JJ (NN + NNUL)
#define JJP 2112
#define SCALE 8.0f
#define LN_EPS 1e-5f
#define MM (BB * NN)

typedef __nv_bfloat16 bf16;

// ---------------- scratch ----------------------------------------------------
__device__ float g_xt[(size_t)MM * DIM];
__device__ float g_xn[(size_t)MM * DIM];
__device__ float g_wqt[(size_t)DIM * DIM];        // transposed [N][K], tf32
__device__ float g_wkvt[(size_t)2 * DIM * DIM];   // transposed [N][K], tf32
__device__ float g_wot[(size_t)DIM * DIM];        // transposed [N][K], tf32
__device__ float g_qraw[(size_t)MM * DIM];
__device__ float g_kvraw[(size_t)MM * 2 * DIM];
__device__ float g_q[(size_t)BB * HH * NN * DH];
__device__ float g_ao[(size_t)MM * DIM];
__device__ bf16 g_kh[(size_t)BB * HH * JJP * DH];
__device__ bf16 g_kl[(size_t)BB * HH * JJP * DH];
__device__ bf16 g_vth[(size_t)BB * HH * DH * JJP];
__device__ bf16 g_vtl[(size_t)BB * HH * DH * JJP];

__device__ __forceinline__ uint32_t to_tf32(float f) {
    uint32_t u;
    asm("cvt.rna.tf32.f32 %0, %1;" : "=r"(u) : "f"(f));
    return u;
}
__device__ __forceinline__ float tf32f(float f) { return __uint_as_float(to_tf32(f)); }

// ---------------- weight transpose + tf32 round: [K][N] -> [N][K] -------------
__global__ void wtconv_kernel(const float* __restrict__ W, float* __restrict__ Wt,
                              int K, int N) {
    __shared__ float t[32][33];
    int tx = threadIdx.x, ty = threadIdx.y;
    int n0 = blockIdx.x * 32, k0 = blockIdx.y * 32;
#pragma unroll
    for (int e = 0; e < 4; e++)
        t[ty + 8 * e][tx] = W[(size_t)(k0 + ty + 8 * e) * N + n0 + tx];
    __syncthreads();
#pragma unroll
    for (int e = 0; e < 4; e++) {
        float v = t[tx][ty + 8 * e];
        int n = n0 + ty + 8 * e, k = k0 + tx;
        Wt[(size_t)n * K + k] = tf32f(v);
    }
}

// ---------------- LayerNorm (emits tf32 xn AND tf32 x) ------------------------
__global__ void ln_kernel(const float* __restrict__ x, const float* __restrict__ gma,
                          const float* __restrict__ bta) {
    int row = blockIdx.x;
    const float* xr = x + (size_t)row * DIM;
    float vals[4];
    float s = 0.f, ss = 0.f;
#pragma unroll
    for (int i = 0; i < 4; i++) {
        float v = xr[threadIdx.x + i * 256];
        vals[i] = v;
        s += v;
        ss += v * v;
    }
#pragma unroll
    for (int off = 16; off; off >>= 1) {
        s += __shfl_xor_sync(0xffffffffu, s, off);
        ss += __shfl_xor_sync(0xffffffffu, ss, off);
    }
    __shared__ float rs[8], rss[8];
    int w = threadIdx.x >> 5;
    if ((threadIdx.x & 31) == 0) { rs[w] = s; rss[w] = ss; }
    __syncthreads();
    if (threadIdx.x < 32) {
        float a = (threadIdx.x < 8) ? rs[threadIdx.x] : 0.f;
        float b2 = (threadIdx.x < 8) ? rss[threadIdx.x] : 0.f;
#pragma unroll
        for (int off = 4; off; off >>= 1) {
            a += __shfl_xor_sync(0xffffffffu, a, off);
            b2 += __shfl_xor_sync(0xffffffffu, b2, off);
        }
        if (threadIdx.x == 0) { rs[0] = a; rss[0] = b2; }
    }
    __syncthreads();
    float mu = rs[0] * (1.0f / DIM);
    float var = rss[0] * (1.0f / DIM) - mu * mu;
    float inv = rsqrtf(var + LN_EPS);
#pragma unroll
    for (int i = 0; i < 4; i++) {
        int d = threadIdx.x + i * 256;
        g_xt[(size_t)row * DIM + d] = tf32f(vals[i]);
        g_xn[(size_t)row * DIM + d] = tf32f((vals[i] - mu) * inv * gma[d] + bta[d]);
    }
}

// ---------------- TF32 GEMM core (3-stage cp.async pipeline) ------------------
#define TBM 128
#define TBN 128
#define TBK 32
#define TSTR 36
#define TILE_FLOATS (128 * TSTR)
#define STAGE_FLOATS (2 * TILE_FLOATS)
#define NSTAGE 3
#define GEMM_SMEM_BYTES (NSTAGE * STAGE_FLOATS * 4)
#define GK DIM
#define GTILES (GK / TBK)

__device__ __forceinline__ void cp_async16(void* sdst, const void* gsrc) {
    uint32_t sa = (uint32_t)__cvta_generic_to_shared(sdst);
    asm volatile("cp.async.cg.shared.global [%0], [%1], 16;\n" :: "r"(sa), "l"(gsrc));
}
__device__ __forceinline__ void cp_commit() {
    asm volatile("cp.async.commit_group;\n" ::: "memory");
}
__device__ __forceinline__ void cp_wait0() {
    asm volatile("cp.async.wait_group 0;\n" ::: "memory");
}
__device__ __forceinline__ void cp_wait1() {
    asm volatile("cp.async.wait_group 1;\n" ::: "memory");
}
#define LDSM_X4(r0, r1, r2, r3, addr)                                        \
    asm volatile("ldmatrix.sync.aligned.m8n8.x4.shared.b16 {%0,%1,%2,%3}, [%4];" \
        : "=r"(r0), "=r"(r1), "=r"(r2), "=r"(r3) : "r"(addr))

__device__ __forceinline__ void gemm_body(const float* __restrict__ A,
                                          const float* __restrict__ Bt,
                                          float* __restrict__ C,
                                          int N, int row0, int col0, float* smem) {
    int tid = threadIdx.x;
    int lane = tid & 31;
    int warp = tid >> 5;
    int wm = warp >> 2;
    int wn = warp & 3;

    float acc[4][4][4];
#pragma unroll
    for (int i = 0; i < 4; i++)
#pragma unroll
        for (int j = 0; j < 4; j++)
#pragma unroll
            for (int r = 0; r < 4; r++) acc[i][j][r] = 0.f;

    int s_r = tid >> 3;
    int s_c4 = (tid & 7) * 4;

    uint32_t smem_u32 = (uint32_t)__cvta_generic_to_shared(smem);

    int ltile = lane >> 3;
    int lrow = lane & 7;
    uint32_t aBase[4];
#pragma unroll
    for (int mt = 0; mt < 4; mt++) {
        int r = wm * 64 + mt * 16 + (ltile & 1) * 8 + lrow;
        aBase[mt] = (uint32_t)((r * TSTR + (ltile >> 1) * 4) * 4);
    }
    uint32_t bBase[2];
#pragma unroll
    for (int p = 0; p < 2; p++) {
        int r = wn * 32 + p * 16 + (ltile >> 1) * 8 + lrow;
        bBase[p] = (uint32_t)(TILE_FLOATS * 4 + (r * TSTR + (ltile & 1) * 4) * 4);
    }

    auto stage_tile = [&](int kt2, int buf) {
        float* As = smem + buf * STAGE_FLOATS;
        float* Bs = As + TILE_FLOATS;
        int kg = kt2 * TBK;
#pragma unroll
        for (int t = 0; t < 4; t++) {
            int r = s_r + t * 32;
            cp_async16(&As[r * TSTR + s_c4], &A[(size_t)(row0 + r) * GK + kg + s_c4]);
            cp_async16(&Bs[r * TSTR + s_c4], &Bt[(size_t)(col0 + r) * GK + kg + s_c4]);
        }
        cp_commit();
    };

    stage_tile(0, 0);
    stage_tile(1, 1);

    int buf = 0;
    for (int kt = 0; kt < GTILES; kt++) {
        if (kt + 1 < GTILES) cp_wait1(); else cp_wait0();
        __syncthreads();
        if (kt + 2 < GTILES) {
            int nb2 = buf + 2;
            if (nb2 >= NSTAGE) nb2 -= NSTAGE;
            stage_tile(kt + 2, nb2);
        }
        uint32_t stage = smem_u32 + (uint32_t)(buf * STAGE_FLOATS * 4);
#pragma unroll
        for (int ks = 0; ks < 4; ks++) {
            uint32_t koff = (uint32_t)(ks * 8 * 4);
            uint32_t af[4][4], bf[4][2];
#pragma unroll
            for (int mt = 0; mt < 4; mt++)
                LDSM_X4(af[mt][0], af[mt][1], af[mt][2], af[mt][3],
                        stage + aBase[mt] + koff);
#pragma unroll
            for (int p = 0; p < 2; p++)
                LDSM_X4(bf[2 * p][0], bf[2 * p][1], bf[2 * p + 1][0], bf[2 * p + 1][1],
                        stage + bBase[p] + koff);
#pragma unroll
            for (int mt = 0; mt < 4; mt++)
#pragma unroll
                for (int nt = 0; nt < 4; nt++) {
                    asm volatile(
                        "mma.sync.aligned.m16n8k8.row.col.f32.tf32.tf32.f32 "
                        "{%0,%1,%2,%3}, {%4,%5,%6,%7}, {%8,%9}, {%0,%1,%2,%3};"
                        : "+f"(acc[mt][nt][0]), "+f"(acc[mt][nt][1]),
                          "+f"(acc[mt][nt][2]), "+f"(acc[mt][nt][3])
                        : "r"(af[mt][0]), "r"(af[mt][1]), "r"(af[mt][2]), "r"(af[mt][3]),
                          "r"(bf[nt][0]), "r"(bf[nt][1]));
                }
        }
        if (++buf == NSTAGE) buf = 0;
    }

    int fr = lane >> 2;
    int fc = lane & 3;
#pragma unroll
    for (int mt = 0; mt < 4; mt++) {
        int row = row0 + wm * 64 + mt * 16 + fr;
#pragma unroll
        for (int nt = 0; nt < 4; nt++) {
            int col = col0 + wn * 32 + nt * 8 + fc * 2;
            *(float2*)&C[(size_t)row * N + col] = make_float2(acc[mt][nt][0], acc[mt][nt][1]);
            *(float2*)&C[(size_t)(row + 8) * N + col] = make_float2(acc[mt][nt][2], acc[mt][nt][3]);
        }
    }
}

__global__ void __launch_bounds__(256, 2)
tf32gemm_qkv() {
    extern __shared__ float smem[];
    const float* A;
    const float* B;
    float* C;
    int N, col0;
    if (blockIdx.x < 8) {
        A = g_xn; B = g_wqt; C = g_qraw; N = DIM; col0 = blockIdx.x * TBN;
    } else {
        A = g_xt; B = g_wkvt; C = g_kvraw; N = 2 * DIM; col0 = (blockIdx.x - 8) * TBN;
    }
    gemm_body(A, B, C, N, blockIdx.y * TBM, col0, smem);
}

__global__ void __launch_bounds__(256, 2)
tf32gemm_o(float* __restrict__ out) {
    extern __shared__ float smem[];
    gemm_body(g_ao, g_wot, out, DIM, blockIdx.y * TBM, blockIdx.x * TBN, smem);
}

// ---------------- preps ------------------------------------------------------
__global__ void qprep_kernel(const float* __restrict__ qs) {
    int gw = blockIdx.x * 4 + (threadIdx.x >> 5);
    int lane = threadIdx.x & 31;
    int h = gw % HH;
    int n = (gw / HH) % NN;
    int b = gw / (HH * NN);
    const float* src = g_qraw + (size_t)(b * NN + n) * DIM + h * DH;
    float v0 = src[lane], v1 = src[lane + 32];
    float ss = v0 * v0 + v1 * v1;
#pragma unroll
    for (int off = 16; off; off >>= 1) ss += __shfl_xor_sync(0xffffffffu, ss, off);
    float inv = 1.0f / fmaxf(sqrtf(ss), 1e-12f);
    float* dst = g_q + (size_t)((b * HH + h) * NN + n) * DH;
    dst[lane] = v0 * inv * qs[lane];
    dst[lane + 32] = v1 * inv * qs[lane + 32];
}

__global__ void kvprep_kernel(const float* __restrict__ ks) {
    int gw = blockIdx.x * 4 + (threadIdx.x >> 5);
    int lane = threadIdx.x & 31;
    int h = gw % HH;
    int n = (gw / HH) % NN;
    int b = gw / (HH * NN);
    const float* row = g_kvraw + (size_t)(b * NN + n) * (2 * DIM);
    float k0 = row[h * DH + lane], k1 = row[h * DH + lane + 32];
    float v0 = row[DIM + h * DH + lane], v1 = row[DIM + h * DH + lane + 32];
    float ss = k0 * k0 + k1 * k1;
#pragma unroll
    for (int off = 16; off; off >>= 1) ss += __shfl_xor_sync(0xffffffffu, ss, off);
    float inv = 1.0f / fmaxf(sqrtf(ss), 1e-12f);
    k0 = k0 * inv * ks[lane];
    k1 = k1 * inv * ks[lane + 32];
    int j = n + NNUL;
    size_t kb = ((size_t)(b * HH + h) * JJP + j) * DH;
    bf16 h0 = __float2bfloat16_rn(k0);
    bf16 h1 = __float2bfloat16_rn(k1);
    g_kh[kb + lane] = h0;
    g_kh[kb + lane + 32] = h1;
    g_kl[kb + lane] = __float2bfloat16_rn(k0 - __bfloat162float(h0));
    g_kl[kb + lane + 32] = __float2bfloat16_rn(k1 - __bfloat162float(h1));
    size_t vb = (size_t)(b * HH + h) * DH * JJP;
    bf16 vh0 = __float2bfloat16_rn(v0);
    bf16 vh1 = __float2bfloat16_rn(v1);
    g_vth[vb + (size_t)lane * JJP + j] = vh0;
    g_vth[vb + (size_t)(lane + 32) * JJP + j] = vh1;
    g_vtl[vb + (size_t)lane * JJP + j] = __float2bfloat16_rn(v0 - __bfloat162float(vh0));
    g_vtl[vb + (size_t)(lane + 32) * JJP + j] = __float2bfloat16_rn(v1 - __bfloat162float(vh1));
}

__global__ void nullprep_kernel(const float* __restrict__ null_kv,
                                const float* __restrict__ ks) {
    int w = threadIdx.x >> 5;
    int lane = threadIdx.x & 31;
    int h = w / NNUL;
    int t = w % NNUL;
    const float* base = null_kv + (size_t)h * (2 * NNUL) * DH;
    float k0 = base[(2 * t) * DH + lane];
    float k1 = base[(2 * t) * DH + lane + 32];
    float v0 = base[(2 * t + 1) * DH + lane];
    float v1 = base[(2 * t + 1) * DH + lane + 32];
    float ss = k0 * k0 + k1 * k1;
#pragma unroll
    for (int off = 16; off; off >>= 1) ss += __shfl_xor_sync(0xffffffffu, ss, off);
    float inv = 1.0f / fmaxf(sqrtf(ss), 1e-12f);
    k0 = k0 * inv * ks[lane];
    k1 = k1 * inv * ks[lane + 32];
    bf16 kh0 = __float2bfloat16_rn(k0), kh1 = __float2bfloat16_rn(k1);
    bf16 kl0 = __float2bfloat16_rn(k0 - __bfloat162float(kh0));
    bf16 kl1 = __float2bfloat16_rn(k1 - __bfloat162float(kh1));
    bf16 vh0 = __float2bfloat16_rn(v0), vh1 = __float2bfloat16_rn(v1);
    bf16 vl0 = __float2bfloat16_rn(v0 - __bfloat162float(vh0));
    bf16 vl1 = __float2bfloat16_rn(v1 - __bfloat162float(vh1));
    for (int b = 0; b < BB; b++) {
        size_t kb = ((size_t)(b * HH + h) * JJP + t) * DH;
        g_kh[kb + lane] = kh0;
        g_kh[kb + lane + 32] = kh1;
        g_kl[kb + lane] = kl0;
        g_kl[kb + lane + 32] = kl1;
        size_t vb = (size_t)(b * HH + h) * DH * JJP;
        g_vth[vb + (size_t)lane * JJP + t] = vh0;
        g_vth[vb + (size_t)(lane + 32) * JJP + t] = vh1;
        g_vtl[vb + (size_t)lane * JJP + t] = vl0;
        g_vtl[vb + (size_t)(lane + 32) * JJP + t] = vl1;
    }
}

// ---------------- mma attention (R12 structure: 64 q-rows, 128 thr) ----------
#define KSTR 72
#define QSTR 68
#define TILE_HB (64 * KSTR * 2)
#define ATTN_SMEM (4 * TILE_HB)

#define MMA_BF16(C, A, B0, B1)                                              \
    asm volatile(                                                           \
        "mma.sync.aligned.m16n8k16.row.col.f32.bf16.bf16.f32 "              \
        "{%0,%1,%2,%3}, {%4,%5,%6,%7}, {%8,%9}, {%0,%1,%2,%3};"             \
        : "+f"(C[0]), "+f"(C[1]), "+f"(C[2]), "+f"(C[3])                    \
        : "r"(A[0]), "r"(A[1]), "r"(A[2]), "r"(A[3]), "r"(B0), "r"(B1))

__device__ __forceinline__ uint32_t pack_bf2(float a, float b) {
    __nv_bfloat162 t;
    t.x = __float2bfloat16_rn(a);
    t.y = __float2bfloat16_rn(b);
    return *(uint32_t*)&t;
}

__global__ void __launch_bounds__(128)
attn_mma_kernel() {
    extern __shared__ char sm[];
    bf16* Kh = (bf16*)sm;
    bf16* Kl = (bf16*)(sm + TILE_HB);
    bf16* Vh = (bf16*)(sm + 2 * TILE_HB);
    bf16* Vl = (bf16*)(sm + 3 * TILE_HB);
    float* Qs = (float*)sm;

    int b = blockIdx.z, h = blockIdx.y;
    int qt = (gridDim.x - 1) - blockIdx.x;
    int tid = threadIdx.x;
    int w = tid >> 5;
    int lane = tid & 31;
    int fr = lane >> 2;
    int fc = lane & 3;

    size_t qbase = (size_t)((b * HH + h) * NN + qt * 64) * DH;
    const char* kh_b = (const char*)(g_kh + (size_t)(b * HH + h) * JJP * DH);
    const char* kl_b = (const char*)(g_kl + (size_t)(b * HH + h) * JJP * DH);
    const char* vth_b = (const char*)(g_vth + (size_t)(b * HH + h) * DH * JJP);
    const char* vtl_b = (const char*)(g_vtl + (size_t)(b * HH + h) * DH * JJP);

    for (int i = tid; i < 64 * 16; i += 128) {
        int r = i >> 4, c4 = (i & 15) * 4;
        *(float4*)&Qs[r * QSTR + c4] = *(const float4*)&g_q[qbase + (size_t)r * DH + c4];
    }
    __syncthreads();

    uint32_t qh[4][4], ql[4][4];
#pragma unroll
    for (int kc = 0; kc < 4; kc++) {
        int lr = w * 16 + fr;
        int c = kc * 16 + 2 * fc;
#pragma unroll
        for (int p = 0; p < 4; p++) {
            int rr = lr + (p & 1) * 8;
            int cc = c + (p >> 1) * 8;
            float x0 = Qs[rr * QSTR + cc], x1 = Qs[rr * QSTR + cc + 1];
            float h0 = __bfloat162float(__float2bfloat16_rn(x0));
            float h1 = __bfloat162float(__float2bfloat16_rn(x1));
            qh[kc][p] = pack_bf2(h0, h1);
            ql[kc][p] = pack_bf2(x0 - h0, x1 - h1);
        }
    }

    float O[8][4];
#pragma unroll
    for (int nb = 0; nb < 8; nb++)
#pragma unroll
        for (int r = 0; r < 4; r++) O[nb][r] = 0.f;

    float slope = exp2f(-0.5f * (float)(h + 1));
    int row0g = qt * 64 + w * 16 + fr;
    int row1g = row0g + 8;
    int my0 = row0g + NNUL, my1 = row1g + NNUL;
    float m0 = -1e30f, m1 = -1e30f, l0 = 0.f, l1 = 0.f;

    int nkeys = min(qt * 64 + 64 + NNUL, JJ);

    for (int j0 = 0; j0 < nkeys; j0 += 64) {
        __syncthreads();
        for (int i = tid; i < 64 * 8; i += 128) {
            int r = i >> 3, c = i & 7;
            uint32_t doff = r * 144 + c * 16;
            cp_async16(sm + 0 * TILE_HB + doff, kh_b + (size_t)(j0 + r) * 128 + c * 16);
            cp_async16(sm + 1 * TILE_HB + doff, kl_b + (size_t)(j0 + r) * 128 + c * 16);
            cp_async16(sm + 2 * TILE_HB + doff, vth_b + (size_t)r * (JJP * 2) + j0 * 2 + c * 16);
            cp_async16(sm + 3 * TILE_HB + doff, vtl_b + (size_t)r * (JJP * 2) + j0 * 2 + c * 16);
        }
        cp_commit();
        cp_wait0();
        __syncthreads();

        float S[8][4];
#pragma unroll
        for (int nb = 0; nb < 8; nb++)
#pragma unroll
            for (int r = 0; r < 4; r++) S[nb][r] = 0.f;

#pragma unroll
        for (int kc = 0; kc < 4; kc++) {
#pragma unroll
            for (int nb = 0; nb < 8; nb++) {
                int krow = nb * 8 + fr;
                int kcol = kc * 16 + 2 * fc;
                uint32_t b0h = *(uint32_t*)&Kh[krow * KSTR + kcol];
                uint32_t b1h = *(uint32_t*)&Kh[krow * KSTR + kcol + 8];
                uint32_t b0l = *(uint32_t*)&Kl[krow * KSTR + kcol];
                uint32_t b1l = *(uint32_t*)&Kl[krow * KSTR + kcol + 8];
                MMA_BF16(S[nb], qh[kc], b0h, b1h);
                MMA_BF16(S[nb], qh[kc], b0l, b1l);
                MMA_BF16(S[nb], ql[kc], b0h, b1h);
            }
        }

        float mt0 = -1e30f, mt1 = -1e30f;
#pragma unroll
        for (int nb = 0; nb < 8; nb++) {
#pragma unroll
            for (int e = 0; e < 2; e++) {
                int col = j0 + nb * 8 + 2 * fc + e;
                float s0 = S[nb][e] * SCALE + slope * (float)(col - my0);
                if (col > my0) s0 = -1e30f;
                S[nb][e] = s0;
                mt0 = fmaxf(mt0, s0);
                float s1 = S[nb][2 + e] * SCALE + slope * (float)(col - my1);
                if (col > my1) s1 = -1e30f;
                S[nb][2 + e] = s1;
                mt1 = fmaxf(mt1, s1);
            }
        }
#pragma unroll
        for (int off = 1; off <= 2; off <<= 1) {
            mt0 = fmaxf(mt0, __shfl_xor_sync(0xffffffffu, mt0, off));
            mt1 = fmaxf(mt1, __shfl_xor_sync(0xffffffffu, mt1, off));
        }
        float mn0 = fmaxf(m0, mt0), mn1 = fmaxf(m1, mt1);
        float c0 = __expf(m0 - mn0), c1 = __expf(m1 - mn1);
        m0 = mn0; m1 = mn1;

        float ps0 = 0.f, ps1 = 0.f;
#pragma unroll
        for (int nb = 0; nb < 8; nb++) {
#pragma unroll
            for (int e = 0; e < 2; e++) {
                float p0 = __expf(S[nb][e] - m0);
                float p1 = __expf(S[nb][2 + e] - m1);
                S[nb][e] = p0; S[nb][2 + e] = p1;
                ps0 += p0; ps1 += p1;
            }
        }
        l0 = l0 * c0 + ps0;
        l1 = l1 * c1 + ps1;
#pragma unroll
        for (int nb = 0; nb < 8; nb++) {
            O[nb][0] *= c0; O[nb][1] *= c0;
            O[nb][2] *= c1; O[nb][3] *= c1;
        }

        uint32_t ph[4][4], pl[4][4];
#pragma unroll
        for (int kc = 0; kc < 4; kc++) {
#pragma unroll
            for (int p = 0; p < 4; p++) {
                float x0 = S[2 * kc + (p >> 1)][(p & 1) * 2 + 0];
                float x1 = S[2 * kc + (p >> 1)][(p & 1) * 2 + 1];
                float h0 = __bfloat162float(__float2bfloat16_rn(x0));
                float h1 = __bfloat162float(__float2bfloat16_rn(x1));
                ph[kc][p] = pack_bf2(h0, h1);
                pl[kc][p] = pack_bf2(x0 - h0, x1 - h1);
            }
        }

#pragma unroll
        for (int kc = 0; kc < 4; kc++) {
#pragma unroll
            for (int nb = 0; nb < 8; nb++) {
                int drow = nb * 8 + fr;
                int kcol = kc * 16 + 2 * fc;
                uint32_t b0h = *(uint32_t*)&Vh[drow * KSTR + kcol];
                uint32_t b1h = *(uint32_t*)&Vh[drow * KSTR + kcol + 8];
                uint32_t b0l = *(uint32_t*)&Vl[drow * KSTR + kcol];
                uint32_t b1l = *(uint32_t*)&Vl[drow * KSTR + kcol + 8];
                MMA_BF16(O[nb], ph[kc], b0h, b1h);
                MMA_BF16(O[nb], ph[kc], b0l, b1l);
                MMA_BF16(O[nb], pl[kc], b0h, b1h);
            }
        }
    }

#pragma unroll
    for (int off = 1; off <= 2; off <<= 1) {
        l0 += __shfl_xor_sync(0xffffffffu, l0, off);
        l1 += __shfl_xor_sync(0xffffffffu, l1, off);
    }
    float i0 = 1.0f / l0, i1 = 1.0f / l1;
#pragma unroll
    for (int nb = 0; nb < 8; nb++) {
        int col = h * DH + nb * 8 + 2 * fc;
        *(float2*)&g_ao[(size_t)(b * NN + row0g) * DIM + col] =
            make_float2(tf32f(O[nb][0] * i0), tf32f(O[nb][1] * i0));
        *(float2*)&g_ao[(size_t)(b * NN + row1g) * DIM + col] =
            make_float2(tf32f(O[nb][2] * i1), tf32f(O[nb][3] * i1));
    }
}

// ---------------- launch -----------------------------------------------------
extern "C" void kernel_launch(void* const* d_in, const int* in_sizes, int n_in,
                              void* d_out, int out_size) {
    const float* x = (const float*)d_in[0];
    const float* norm_g = (const float*)d_in[1];
    const float* norm_b = (const float*)d_in[2];
    const float* Wq = (const float*)d_in[3];
    const float* Wkv = (const float*)d_in[4];
    const float* q_scale = (const float*)d_in[5];
    const float* k_scale = (const float*)d_in[6];
    const float* null_kv = (const float*)d_in[7];
    const float* Wout = (const float*)d_in[8];
    float* out = (float*)d_out;

    float *p_wqt, *p_wkvt, *p_wot;
    cudaGetSymbolAddress((void**)&p_wqt, g_wqt);
    cudaGetSymbolAddress((void**)&p_wkvt, g_wkvt);
    cudaGetSymbolAddress((void**)&p_wot, g_wot);

    static int smem_set = 0;
    if (!smem_set) {
        cudaFuncSetAttribute(tf32gemm_qkv, cudaFuncAttributeMaxDynamicSharedMemorySize,
                             GEMM_SMEM_BYTES);
        cudaFuncSetAttribute(tf32gemm_o, cudaFuncAttributeMaxDynamicSharedMemorySize,
                             GEMM_SMEM_BYTES);
        cudaFuncSetAttribute(attn_mma_kernel, cudaFuncAttributeMaxDynamicSharedMemorySize,
                             ATTN_SMEM);
        smem_set = 1;
    }

    wtconv_kernel<<<dim3(DIM / 32, DIM / 32), dim3(32, 8)>>>(Wq, p_wqt, DIM, DIM);
    wtconv_kernel<<<dim3(2 * DIM / 32, DIM / 32), dim3(32, 8)>>>(Wkv, p_wkvt, DIM, 2 * DIM);
    ln_kernel<<<MM, 256>>>(x, norm_g, norm_b);

    tf32gemm_qkv<<<dim3(24, MM / TBM), 256, GEMM_SMEM_BYTES>>>();

    wtconv_kernel<<<dim3(DIM / 32, DIM / 32), dim3(32, 8)>>>(Wout, p_wot, DIM, DIM);

    qprep_kernel<<<(BB * NN * HH) / 4, 128>>>(q_scale);
    kvprep_kernel<<<(BB * NN * HH) / 4, 128>>>(k_scale);
    nullprep_kernel<<<1, HH * NNUL * 32>>>(null_kv, k_scale);

    attn_mma_kernel<<<dim3(NN / 64, HH, BB), 128, ATTN_SMEM>>>();

    tf32gemm_o<<<dim3(DIM / TBN, MM / TBM), 256, GEMM_SMEM_BYTES>>>(out);
}

// round 17
// speedup vs baseline: 1.0976x; 1.0269x over previous
#include <cuda_runtime.h>
#include <cuda_bf16.h>
#include <math.h>
#include <stdint.h>

#define BB 2
#define NN 2048
#define DIM 1024
#define HH 16
#define DH 64
#define NNUL 2
#define JJ (NN + NNUL)
#define JJP 2112
#define SCALE 8.0f
#define LN_EPS 1e-5f
#define MM (BB * NN)

typedef __nv_bfloat16 bf16;

// ---------------- scratch ----------------------------------------------------
__device__ float g_xt[(size_t)MM * DIM];
__device__ float g_xn[(size_t)MM * DIM];
__device__ float g_wqt[(size_t)DIM * DIM];        // transposed [N][K], tf32
__device__ float g_wkvt[(size_t)2 * DIM * DIM];   // transposed [N][K], tf32
__device__ float g_wot[(size_t)DIM * DIM];        // transposed [N][K], tf32
__device__ float g_qraw[(size_t)MM * DIM];
__device__ float g_kvraw[(size_t)MM * 2 * DIM];
__device__ float g_q[(size_t)BB * HH * NN * DH];
__device__ float g_ao[(size_t)MM * DIM];
__device__ bf16 g_kh[(size_t)BB * HH * JJP * DH];
__device__ bf16 g_kl[(size_t)BB * HH * JJP * DH];
__device__ bf16 g_vth[(size_t)BB * HH * DH * JJP];
__device__ bf16 g_vtl[(size_t)BB * HH * DH * JJP];

__device__ __forceinline__ uint32_t to_tf32(float f) {
    uint32_t u;
    asm("cvt.rna.tf32.f32 %0, %1;" : "=r"(u) : "f"(f));
    return u;
}
__device__ __forceinline__ float tf32f(float f) { return __uint_as_float(to_tf32(f)); }

// ---------------- fused weight transpose + tf32 round -------------------------
// x-tile 0..31 -> Wq ; 32..95 -> Wkv ; 96..127 -> Wout  (all K=DIM)
__global__ void wtconv_all(const float* __restrict__ Wq, const float* __restrict__ Wkv,
                           const float* __restrict__ Wout) {
    __shared__ float t[32][33];
    int xt = blockIdx.x;
    const float* W;
    float* Wt;
    int N;
    if (xt < 32) { W = Wq; Wt = g_wqt; N = DIM; }
    else if (xt < 96) { W = Wkv; Wt = g_wkvt; N = 2 * DIM; xt -= 32; }
    else { W = Wout; Wt = g_wot; N = DIM; xt -= 96; }
    int tx = threadIdx.x, ty = threadIdx.y;
    int n0 = xt * 32, k0 = blockIdx.y * 32;
#pragma unroll
    for (int e = 0; e < 4; e++)
        t[ty + 8 * e][tx] = W[(size_t)(k0 + ty + 8 * e) * N + n0 + tx];
    __syncthreads();
#pragma unroll
    for (int e = 0; e < 4; e++) {
        float v = t[tx][ty + 8 * e];
        int n = n0 + ty + 8 * e, k = k0 + tx;
        Wt[(size_t)n * DIM + k] = tf32f(v);
    }
}

// ---------------- LayerNorm (emits tf32 xn AND tf32 x) ------------------------
__global__ void ln_kernel(const float* __restrict__ x, const float* __restrict__ gma,
                          const float* __restrict__ bta) {
    int row = blockIdx.x;
    const float* xr = x + (size_t)row * DIM;
    float vals[4];
    float s = 0.f, ss = 0.f;
#pragma unroll
    for (int i = 0; i < 4; i++) {
        float v = xr[threadIdx.x + i * 256];
        vals[i] = v;
        s += v;
        ss += v * v;
    }
#pragma unroll
    for (int off = 16; off; off >>= 1) {
        s += __shfl_xor_sync(0xffffffffu, s, off);
        ss += __shfl_xor_sync(0xffffffffu, ss, off);
    }
    __shared__ float rs[8], rss[8];
    int w = threadIdx.x >> 5;
    if ((threadIdx.x & 31) == 0) { rs[w] = s; rss[w] = ss; }
    __syncthreads();
    if (threadIdx.x < 32) {
        float a = (threadIdx.x < 8) ? rs[threadIdx.x] : 0.f;
        float b2 = (threadIdx.x < 8) ? rss[threadIdx.x] : 0.f;
#pragma unroll
        for (int off = 4; off; off >>= 1) {
            a += __shfl_xor_sync(0xffffffffu, a, off);
            b2 += __shfl_xor_sync(0xffffffffu, b2, off);
        }
        if (threadIdx.x == 0) { rs[0] = a; rss[0] = b2; }
    }
    __syncthreads();
    float mu = rs[0] * (1.0f / DIM);
    float var = rss[0] * (1.0f / DIM) - mu * mu;
    float inv = rsqrtf(var + LN_EPS);
#pragma unroll
    for (int i = 0; i < 4; i++) {
        int d = threadIdx.x + i * 256;
        g_xt[(size_t)row * DIM + d] = tf32f(vals[i]);
        g_xn[(size_t)row * DIM + d] = tf32f((vals[i] - mu) * inv * gma[d] + bta[d]);
    }
}

// ---------------- TF32 GEMM core (3-stage cp.async pipeline) ------------------
#define TBM 128
#define TBN 128
#define TBK 32
#define TSTR 36
#define TILE_FLOATS (128 * TSTR)
#define STAGE_FLOATS (2 * TILE_FLOATS)
#define NSTAGE 3
#define GEMM_SMEM_BYTES (NSTAGE * STAGE_FLOATS * 4)
#define GK DIM
#define GTILES (GK / TBK)

__device__ __forceinline__ void cp_async16(void* sdst, const void* gsrc) {
    uint32_t sa = (uint32_t)__cvta_generic_to_shared(sdst);
    asm volatile("cp.async.cg.shared.global [%0], [%1], 16;\n" :: "r"(sa), "l"(gsrc));
}
__device__ __forceinline__ void cp_commit() {
    asm volatile("cp.async.commit_group;\n" ::: "memory");
}
__device__ __forceinline__ void cp_wait0() {
    asm volatile("cp.async.wait_group 0;\n" ::: "memory");
}
__device__ __forceinline__ void cp_wait1() {
    asm volatile("cp.async.wait_group 1;\n" ::: "memory");
}
#define LDSM_X4(r0, r1, r2, r3, addr)                                        \
    asm volatile("ldmatrix.sync.aligned.m8n8.x4.shared.b16 {%0,%1,%2,%3}, [%4];" \
        : "=r"(r0), "=r"(r1), "=r"(r2), "=r"(r3) : "r"(addr))

__device__ __forceinline__ void gemm_body(const float* __restrict__ A,
                                          const float* __restrict__ Bt,
                                          float* __restrict__ C,
                                          int N, int row0, int col0, float* smem) {
    int tid = threadIdx.x;
    int lane = tid & 31;
    int warp = tid >> 5;
    int wm = warp >> 2;
    int wn = warp & 3;

    float acc[4][4][4];
#pragma unroll
    for (int i = 0; i < 4; i++)
#pragma unroll
        for (int j = 0; j < 4; j++)
#pragma unroll
            for (int r = 0; r < 4; r++) acc[i][j][r] = 0.f;

    int s_r = tid >> 3;
    int s_c4 = (tid & 7) * 4;

    uint32_t smem_u32 = (uint32_t)__cvta_generic_to_shared(smem);

    int ltile = lane >> 3;
    int lrow = lane & 7;
    uint32_t aBase[4];
#pragma unroll
    for (int mt = 0; mt < 4; mt++) {
        int r = wm * 64 + mt * 16 + (ltile & 1) * 8 + lrow;
        aBase[mt] = (uint32_t)((r * TSTR + (ltile >> 1) * 4) * 4);
    }
    uint32_t bBase[2];
#pragma unroll
    for (int p = 0; p < 2; p++) {
        int r = wn * 32 + p * 16 + (ltile >> 1) * 8 + lrow;
        bBase[p] = (uint32_t)(TILE_FLOATS * 4 + (r * TSTR + (ltile & 1) * 4) * 4);
    }

    auto stage_tile = [&](int kt2, int buf) {
        float* As = smem + buf * STAGE_FLOATS;
        float* Bs = As + TILE_FLOATS;
        int kg = kt2 * TBK;
#pragma unroll
        for (int t = 0; t < 4; t++) {
            int r = s_r + t * 32;
            cp_async16(&As[r * TSTR + s_c4], &A[(size_t)(row0 + r) * GK + kg + s_c4]);
            cp_async16(&Bs[r * TSTR + s_c4], &Bt[(size_t)(col0 + r) * GK + kg + s_c4]);
        }
        cp_commit();
    };

    stage_tile(0, 0);
    stage_tile(1, 1);

    int buf = 0;
    for (int kt = 0; kt < GTILES; kt++) {
        if (kt + 1 < GTILES) cp_wait1(); else cp_wait0();
        __syncthreads();
        if (kt + 2 < GTILES) {
            int nb2 = buf + 2;
            if (nb2 >= NSTAGE) nb2 -= NSTAGE;
            stage_tile(kt + 2, nb2);
        }
        uint32_t stage = smem_u32 + (uint32_t)(buf * STAGE_FLOATS * 4);
#pragma unroll
        for (int ks = 0; ks < 4; ks++) {
            uint32_t koff = (uint32_t)(ks * 8 * 4);
            uint32_t af[4][4], bf[4][2];
#pragma unroll
            for (int mt = 0; mt < 4; mt++)
                LDSM_X4(af[mt][0], af[mt][1], af[mt][2], af[mt][3],
                        stage + aBase[mt] + koff);
#pragma unroll
            for (int p = 0; p < 2; p++)
                LDSM_X4(bf[2 * p][0], bf[2 * p][1], bf[2 * p + 1][0], bf[2 * p + 1][1],
                        stage + bBase[p] + koff);
#pragma unroll
            for (int mt = 0; mt < 4; mt++)
#pragma unroll
                for (int nt = 0; nt < 4; nt++) {
                    asm volatile(
                        "mma.sync.aligned.m16n8k8.row.col.f32.tf32.tf32.f32 "
                        "{%0,%1,%2,%3}, {%4,%5,%6,%7}, {%8,%9}, {%0,%1,%2,%3};"
                        : "+f"(acc[mt][nt][0]), "+f"(acc[mt][nt][1]),
                          "+f"(acc[mt][nt][2]), "+f"(acc[mt][nt][3])
                        : "r"(af[mt][0]), "r"(af[mt][1]), "r"(af[mt][2]), "r"(af[mt][3]),
                          "r"(bf[nt][0]), "r"(bf[nt][1]));
                }
        }
        if (++buf == NSTAGE) buf = 0;
    }

    int fr = lane >> 2;
    int fc = lane & 3;
#pragma unroll
    for (int mt = 0; mt < 4; mt++) {
        int row = row0 + wm * 64 + mt * 16 + fr;
#pragma unroll
        for (int nt = 0; nt < 4; nt++) {
            int col = col0 + wn * 32 + nt * 8 + fc * 2;
            *(float2*)&C[(size_t)row * N + col] = make_float2(acc[mt][nt][0], acc[mt][nt][1]);
            *(float2*)&C[(size_t)(row + 8) * N + col] = make_float2(acc[mt][nt][2], acc[mt][nt][3]);
        }
    }
}

__global__ void __launch_bounds__(256, 2)
tf32gemm_qkv() {
    extern __shared__ float smem[];
    const float* A;
    const float* B;
    float* C;
    int N, col0;
    if (blockIdx.x < 8) {
        A = g_xn; B = g_wqt; C = g_qraw; N = DIM; col0 = blockIdx.x * TBN;
    } else {
        A = g_xt; B = g_wkvt; C = g_kvraw; N = 2 * DIM; col0 = (blockIdx.x - 8) * TBN;
    }
    gemm_body(A, B, C, N, blockIdx.y * TBM, col0, smem);
}

__global__ void __launch_bounds__(256, 2)
tf32gemm_o(float* __restrict__ out) {
    extern __shared__ float smem[];
    gemm_body(g_ao, g_wot, out, DIM, blockIdx.y * TBM, blockIdx.x * TBN, smem);
}

// ---------------- fused q/kv prep (y=0 -> q, y=1 -> kv) -----------------------
__global__ void qkvprep_kernel(const float* __restrict__ qs, const float* __restrict__ ks) {
    int gw = blockIdx.x * 4 + (threadIdx.x >> 5);
    int lane = threadIdx.x & 31;
    int h = gw % HH;
    int n = (gw / HH) % NN;
    int b = gw / (HH * NN);
    if (blockIdx.y == 0) {
        const float* src = g_qraw + (size_t)(b * NN + n) * DIM + h * DH;
        float v0 = src[lane], v1 = src[lane + 32];
        float ss = v0 * v0 + v1 * v1;
#pragma unroll
        for (int off = 16; off; off >>= 1) ss += __shfl_xor_sync(0xffffffffu, ss, off);
        float inv = 1.0f / fmaxf(sqrtf(ss), 1e-12f);
        float* dst = g_q + (size_t)((b * HH + h) * NN + n) * DH;
        dst[lane] = v0 * inv * qs[lane];
        dst[lane + 32] = v1 * inv * qs[lane + 32];
    } else {
        const float* row = g_kvraw + (size_t)(b * NN + n) * (2 * DIM);
        float k0 = row[h * DH + lane], k1 = row[h * DH + lane + 32];
        float v0 = row[DIM + h * DH + lane], v1 = row[DIM + h * DH + lane + 32];
        float ss = k0 * k0 + k1 * k1;
#pragma unroll
        for (int off = 16; off; off >>= 1) ss += __shfl_xor_sync(0xffffffffu, ss, off);
        float inv = 1.0f / fmaxf(sqrtf(ss), 1e-12f);
        k0 = k0 * inv * ks[lane];
        k1 = k1 * inv * ks[lane + 32];
        int j = n + NNUL;
        size_t kb = ((size_t)(b * HH + h) * JJP + j) * DH;
        bf16 h0 = __float2bfloat16_rn(k0);
        bf16 h1 = __float2bfloat16_rn(k1);
        g_kh[kb + lane] = h0;
        g_kh[kb + lane + 32] = h1;
        g_kl[kb + lane] = __float2bfloat16_rn(k0 - __bfloat162float(h0));
        g_kl[kb + lane + 32] = __float2bfloat16_rn(k1 - __bfloat162float(h1));
        size_t vb = (size_t)(b * HH + h) * DH * JJP;
        bf16 vh0 = __float2bfloat16_rn(v0);
        bf16 vh1 = __float2bfloat16_rn(v1);
        g_vth[vb + (size_t)lane * JJP + j] = vh0;
        g_vth[vb + (size_t)(lane + 32) * JJP + j] = vh1;
        g_vtl[vb + (size_t)lane * JJP + j] = __float2bfloat16_rn(v0 - __bfloat162float(vh0));
        g_vtl[vb + (size_t)(lane + 32) * JJP + j] = __float2bfloat16_rn(v1 - __bfloat162float(vh1));
    }
}

__global__ void nullprep_kernel(const float* __restrict__ null_kv,
                                const float* __restrict__ ks) {
    int w = threadIdx.x >> 5;
    int lane = threadIdx.x & 31;
    int h = w / NNUL;
    int t = w % NNUL;
    const float* base = null_kv + (size_t)h * (2 * NNUL) * DH;
    float k0 = base[(2 * t) * DH + lane];
    float k1 = base[(2 * t) * DH + lane + 32];
    float v0 = base[(2 * t + 1) * DH + lane];
    float v1 = base[(2 * t + 1) * DH + lane + 32];
    float ss = k0 * k0 + k1 * k1;
#pragma unroll
    for (int off = 16; off; off >>= 1) ss += __shfl_xor_sync(0xffffffffu, ss, off);
    float inv = 1.0f / fmaxf(sqrtf(ss), 1e-12f);
    k0 = k0 * inv * ks[lane];
    k1 = k1 * inv * ks[lane + 32];
    bf16 kh0 = __float2bfloat16_rn(k0), kh1 = __float2bfloat16_rn(k1);
    bf16 kl0 = __float2bfloat16_rn(k0 - __bfloat162float(kh0));
    bf16 kl1 = __float2bfloat16_rn(k1 - __bfloat162float(kh1));
    bf16 vh0 = __float2bfloat16_rn(v0), vh1 = __float2bfloat16_rn(v1);
    bf16 vl0 = __float2bfloat16_rn(v0 - __bfloat162float(vh0));
    bf16 vl1 = __float2bfloat16_rn(v1 - __bfloat162float(vh1));
    for (int b = 0; b < BB; b++) {
        size_t kb = ((size_t)(b * HH + h) * JJP + t) * DH;
        g_kh[kb + lane] = kh0;
        g_kh[kb + lane + 32] = kh1;
        g_kl[kb + lane] = kl0;
        g_kl[kb + lane + 32] = kl1;
        size_t vb = (size_t)(b * HH + h) * DH * JJP;
        g_vth[vb + (size_t)lane * JJP + t] = vh0;
        g_vth[vb + (size_t)(lane + 32) * JJP + t] = vh1;
        g_vtl[vb + (size_t)lane * JJP + t] = vl0;
        g_vtl[vb + (size_t)(lane + 32) * JJP + t] = vl1;
    }
}

// ---------------- mma attention: split K/V staging overlap --------------------
#define KSTR 72
#define QSTR 68
#define TILE_HB (64 * KSTR * 2)
#define ATTN_SMEM (4 * TILE_HB)

#define MMA_BF16(C, A, B0, B1)                                              \
    asm volatile(                                                           \
        "mma.sync.aligned.m16n8k16.row.col.f32.bf16.bf16.f32 "              \
        "{%0,%1,%2,%3}, {%4,%5,%6,%7}, {%8,%9}, {%0,%1,%2,%3};"             \
        : "+f"(C[0]), "+f"(C[1]), "+f"(C[2]), "+f"(C[3])                    \
        : "r"(A[0]), "r"(A[1]), "r"(A[2]), "r"(A[3]), "r"(B0), "r"(B1))

__device__ __forceinline__ uint32_t pack_bf2(float a, float b) {
    __nv_bfloat162 t;
    t.x = __float2bfloat16_rn(a);
    t.y = __float2bfloat16_rn(b);
    return *(uint32_t*)&t;
}

__global__ void __launch_bounds__(128)
attn_mma_kernel() {
    extern __shared__ char sm[];
    bf16* Kh = (bf16*)sm;
    bf16* Kl = (bf16*)(sm + TILE_HB);
    bf16* Vh = (bf16*)(sm + 2 * TILE_HB);
    bf16* Vl = (bf16*)(sm + 3 * TILE_HB);
    float* Qs = (float*)sm;

    int b = blockIdx.z, h = blockIdx.y;
    int qt = (gridDim.x - 1) - blockIdx.x;
    int tid = threadIdx.x;
    int w = tid >> 5;
    int lane = tid & 31;
    int fr = lane >> 2;
    int fc = lane & 3;

    size_t qbase = (size_t)((b * HH + h) * NN + qt * 64) * DH;
    const char* kh_b = (const char*)(g_kh + (size_t)(b * HH + h) * JJP * DH);
    const char* kl_b = (const char*)(g_kl + (size_t)(b * HH + h) * JJP * DH);
    const char* vth_b = (const char*)(g_vth + (size_t)(b * HH + h) * DH * JJP);
    const char* vtl_b = (const char*)(g_vtl + (size_t)(b * HH + h) * DH * JJP);

    // ---- stage Q, extract fragments, free the overlay ----
    for (int i = tid; i < 64 * 16; i += 128) {
        int r = i >> 4, c4 = (i & 15) * 4;
        *(float4*)&Qs[r * QSTR + c4] = *(const float4*)&g_q[qbase + (size_t)r * DH + c4];
    }
    __syncthreads();

    uint32_t qh[4][4], ql[4][4];
#pragma unroll
    for (int kc = 0; kc < 4; kc++) {
        int lr = w * 16 + fr;
        int c = kc * 16 + 2 * fc;
#pragma unroll
        for (int p = 0; p < 4; p++) {
            int rr = lr + (p & 1) * 8;
            int cc = c + (p >> 1) * 8;
            float x0 = Qs[rr * QSTR + cc], x1 = Qs[rr * QSTR + cc + 1];
            float h0 = __bfloat162float(__float2bfloat16_rn(x0));
            float h1 = __bfloat162float(__float2bfloat16_rn(x1));
            qh[kc][p] = pack_bf2(h0, h1);
            ql[kc][p] = pack_bf2(x0 - h0, x1 - h1);
        }
    }
    __syncthreads();   // Qs dead; smem free for K/V staging

    float O[8][4];
#pragma unroll
    for (int nb = 0; nb < 8; nb++)
#pragma unroll
        for (int r = 0; r < 4; r++) O[nb][r] = 0.f;

    float slope = exp2f(-0.5f * (float)(h + 1));
    int row0g = qt * 64 + w * 16 + fr;
    int row1g = row0g + 8;
    int my0 = row0g + NNUL, my1 = row1g + NNUL;
    float m0 = -1e30f, m1 = -1e30f, l0 = 0.f, l1 = 0.f;

    int nkeys = min(qt * 64 + 64 + NNUL, JJ);
    int T = (nkeys + 63) / 64;

    // K staging: 4 iters x 2 cp.async per thread; V the same
#define STAGE_K(jt)                                                             \
    do {                                                                        \
        int j0s = (jt) * 64;                                                    \
        for (int i = tid; i < 64 * 8; i += 128) {                               \
            int r = i >> 3, c = i & 7;                                          \
            uint32_t doff = r * 144 + c * 16;                                   \
            cp_async16(sm + 0 * TILE_HB + doff, kh_b + (size_t)(j0s + r) * 128 + c * 16); \
            cp_async16(sm + 1 * TILE_HB + doff, kl_b + (size_t)(j0s + r) * 128 + c * 16); \
        }                                                                       \
        cp_commit();                                                            \
    } while (0)
#define STAGE_V(jt)                                                             \
    do {                                                                        \
        int j0s = (jt) * 64;                                                    \
        for (int i = tid; i < 64 * 8; i += 128) {                               \
            int r = i >> 3, c = i & 7;                                          \
            uint32_t doff = r * 144 + c * 16;                                   \
            cp_async16(sm + 2 * TILE_HB + doff, vth_b + (size_t)r * (JJP * 2) + j0s * 2 + c * 16); \
            cp_async16(sm + 3 * TILE_HB + doff, vtl_b + (size_t)r * (JJP * 2) + j0s * 2 + c * 16); \
        }                                                                       \
        cp_commit();                                                            \
    } while (0)

    STAGE_K(0);
    STAGE_V(0);

    for (int t = 0; t < T; t++) {
        int j0 = t * 64;
        // need K(t): pending groups are {K(t), V(t)} -> wait 1 leaves V(t) in flight
        cp_wait1();
        __syncthreads();

        float S[8][4];
#pragma unroll
        for (int nb = 0; nb < 8; nb++)
#pragma unroll
            for (int r = 0; r < 4; r++) S[nb][r] = 0.f;

#pragma unroll
        for (int kc = 0; kc < 4; kc++) {
#pragma unroll
            for (int nb = 0; nb < 8; nb++) {
                int krow = nb * 8 + fr;
                int kcol = kc * 16 + 2 * fc;
                uint32_t b0h = *(uint32_t*)&Kh[krow * KSTR + kcol];
                uint32_t b1h = *(uint32_t*)&Kh[krow * KSTR + kcol + 8];
                uint32_t b0l = *(uint32_t*)&Kl[krow * KSTR + kcol];
                uint32_t b1l = *(uint32_t*)&Kl[krow * KSTR + kcol + 8];
                MMA_BF16(S[nb], qh[kc], b0h, b1h);
                MMA_BF16(S[nb], qh[kc], b0l, b1l);
                MMA_BF16(S[nb], ql[kc], b0h, b1h);
            }
        }

        float mt0 = -1e30f, mt1 = -1e30f;
#pragma unroll
        for (int nb = 0; nb < 8; nb++) {
#pragma unroll
            for (int e = 0; e < 2; e++) {
                int col = j0 + nb * 8 + 2 * fc + e;
                float s0 = S[nb][e] * SCALE + slope * (float)(col - my0);
                if (col > my0) s0 = -1e30f;
                S[nb][e] = s0;
                mt0 = fmaxf(mt0, s0);
                float s1 = S[nb][2 + e] * SCALE + slope * (float)(col - my1);
                if (col > my1) s1 = -1e30f;
                S[nb][2 + e] = s1;
                mt1 = fmaxf(mt1, s1);
            }
        }
#pragma unroll
        for (int off = 1; off <= 2; off <<= 1) {
            mt0 = fmaxf(mt0, __shfl_xor_sync(0xffffffffu, mt0, off));
            mt1 = fmaxf(mt1, __shfl_xor_sync(0xffffffffu, mt1, off));
        }
        float mn0 = fmaxf(m0, mt0), mn1 = fmaxf(m1, mt1);
        float c0 = __expf(m0 - mn0), c1 = __expf(m1 - mn1);
        m0 = mn0; m1 = mn1;

        float ps0 = 0.f, ps1 = 0.f;
#pragma unroll
        for (int nb = 0; nb < 8; nb++) {
#pragma unroll
            for (int e = 0; e < 2; e++) {
                float p0 = __expf(S[nb][e] - m0);
                float p1 = __expf(S[nb][2 + e] - m1);
                S[nb][e] = p0; S[nb][2 + e] = p1;
                ps0 += p0; ps1 += p1;
            }
        }
        l0 = l0 * c0 + ps0;
        l1 = l1 * c1 + ps1;
#pragma unroll
        for (int nb = 0; nb < 8; nb++) {
            O[nb][0] *= c0; O[nb][1] *= c0;
            O[nb][2] *= c1; O[nb][3] *= c1;
        }

        uint32_t ph[4][4], pl[4][4];
#pragma unroll
        for (int kc = 0; kc < 4; kc++) {
#pragma unroll
            for (int p = 0; p < 4; p++) {
                float x0 = S[2 * kc + (p >> 1)][(p & 1) * 2 + 0];
                float x1 = S[2 * kc + (p >> 1)][(p & 1) * 2 + 1];
                float h0 = __bfloat162float(__float2bfloat16_rn(x0));
                float h1 = __bfloat162float(__float2bfloat16_rn(x1));
                ph[kc][p] = pack_bf2(h0, h1);
                pl[kc][p] = pack_bf2(x0 - h0, x1 - h1);
            }
        }

        // K buffer dead: restage K(t+1) to overlap with O += P.V
        if (t + 1 < T) {
            __syncthreads();        // all warps done reading Kh/Kl
            STAGE_K(t + 1);
            cp_wait1();             // pending {V(t), K(t+1)} -> V(t) complete
        } else {
            cp_wait0();             // only V(t) pending
        }
        __syncthreads();            // V(t) visible to all

#pragma unroll
        for (int kc = 0; kc < 4; kc++) {
#pragma unroll
            for (int nb = 0; nb < 8; nb++) {
                int drow = nb * 8 + fr;
                int kcol = kc * 16 + 2 * fc;
                uint32_t b0h = *(uint32_t*)&Vh[drow * KSTR + kcol];
                uint32_t b1h = *(uint32_t*)&Vh[drow * KSTR + kcol + 8];
                uint32_t b0l = *(uint32_t*)&Vl[drow * KSTR + kcol];
                uint32_t b1l = *(uint32_t*)&Vl[drow * KSTR + kcol + 8];
                MMA_BF16(O[nb], ph[kc], b0h, b1h);
                MMA_BF16(O[nb], ph[kc], b0l, b1l);
                MMA_BF16(O[nb], pl[kc], b0h, b1h);
            }
        }

        // V buffer dead: restage V(t+1) to overlap with next tile's S phase
        if (t + 1 < T) {
            __syncthreads();        // all warps done reading Vh/Vl
            STAGE_V(t + 1);
        }
    }

#pragma unroll
    for (int off = 1; off <= 2; off <<= 1) {
        l0 += __shfl_xor_sync(0xffffffffu, l0, off);
        l1 += __shfl_xor_sync(0xffffffffu, l1, off);
    }
    float i0 = 1.0f / l0, i1 = 1.0f / l1;
#pragma unroll
    for (int nb = 0; nb < 8; nb++) {
        int col = h * DH + nb * 8 + 2 * fc;
        *(float2*)&g_ao[(size_t)(b * NN + row0g) * DIM + col] =
            make_float2(tf32f(O[nb][0] * i0), tf32f(O[nb][1] * i0));
        *(float2*)&g_ao[(size_t)(b * NN + row1g) * DIM + col] =
            make_float2(tf32f(O[nb][2] * i1), tf32f(O[nb][3] * i1));
    }
}

// ---------------- launch -----------------------------------------------------
extern "C" void kernel_launch(void* const* d_in, const int* in_sizes, int n_in,
                              void* d_out, int out_size) {
    const float* x = (const float*)d_in[0];
    const float* norm_g = (const float*)d_in[1];
    const float* norm_b = (const float*)d_in[2];
    const float* Wq = (const float*)d_in[3];
    const float* Wkv = (const float*)d_in[4];
    const float* q_scale = (const float*)d_in[5];
    const float* k_scale = (const float*)d_in[6];
    const float* null_kv = (const float*)d_in[7];
    const float* Wout = (const float*)d_in[8];
    float* out = (float*)d_out;

    static int smem_set = 0;
    if (!smem_set) {
        cudaFuncSetAttribute(tf32gemm_qkv, cudaFuncAttributeMaxDynamicSharedMemorySize,
                             GEMM_SMEM_BYTES);
        cudaFuncSetAttribute(tf32gemm_o, cudaFuncAttributeMaxDynamicSharedMemorySize,
                             GEMM_SMEM_BYTES);
        cudaFuncSetAttribute(attn_mma_kernel, cudaFuncAttributeMaxDynamicSharedMemorySize,
                             ATTN_SMEM);
        smem_set = 1;
    }

    // 1: null kv prep (independent of everything downstream of x)
    nullprep_kernel<<<1, HH * NNUL * 32>>>(null_kv, k_scale);
    // 2: all weight transpose-converts in one launch
    wtconv_all<<<dim3(128, 32), dim3(32, 8)>>>(Wq, Wkv, Wout);
    // 3: LayerNorm
    ln_kernel<<<MM, 256>>>(x, norm_g, norm_b);
    // 4: fused Q + KV projections (ncu sample slot)
    tf32gemm_qkv<<<dim3(24, MM / TBM), 256, GEMM_SMEM_BYTES>>>();
    // 5: fused q/kv prep
    qkvprep_kernel<<<dim3((BB * NN * HH) / 4, 2), 128>>>(q_scale, k_scale);
    // 6: attention
    attn_mma_kernel<<<dim3(NN / 64, HH, BB), 128, ATTN_SMEM>>>();
    // 7: output projection
    tf32gemm_o<<<dim3(DIM / TBN, MM / TBM), 256, GEMM_SMEM_BYTES>>>(out);
}